// round 9
// baseline (speedup 1.0000x reference)
#include <cuda_runtime.h>
#include <cuda_bf16.h>

// Problem constants (fixed by the dataset): B=32, L=256, V=50000, C=128
#define CC   128
#define LL   256
#define BDIM 512

__device__ __forceinline__ float frcp_ap(float x) {
    float r; asm("rcp.approx.f32 %0, %1;" : "=f"(r) : "f"(x)); return r;
}

__global__ __launch_bounds__(BDIM, 1)
void crf_fwd_kernel(const int*   __restrict__ tokens,
                    const int*   __restrict__ target,
                    const float* __restrict__ mask,
                    const float* __restrict__ st,      // state_table [V, C]
                    const float* __restrict__ trans,   // trans_matrix [C, C]
                    float*       __restrict__ out)     // [B]
{
    // p (exp-domain partition vector), double buffered.
    // Stored by state index i at word (i>>5)*36 + (i&31): the four 32-float
    // quarters start at words 0/36/72/108 -> the 4 per-warp broadcast LDS.128
    // addresses land on disjoint banks for every k. 16B aligned for float4.
    __shared__ __align__(16) float p_s[2][144];
    __shared__ int   tok_s[LL];
    __shared__ float m_s[LL];
    __shared__ float red_s[16], red2_s[16];

    const int b   = blockIdx.x;
    const int tid = threadIdx.x;
    const int w   = tid >> 5;
    const int l   = tid & 31;
    const int j   = w * 8 + (l & 7);  // state index 0..127
    const int q   = l >> 3;           // i-quarter 0..3 (32 i's each)

    // ---- stage tokens/mask + target-path energy partial ----
    float tgt_part = 0.0f;
    if (tid < LL) {
        tok_s[tid] = tokens[b * LL + tid];
        m_s[tid]   = mask[b * LL + tid];
        const int t    = tid;
        const int tg   = target[b * LL + t];
        const int prev = (t == 0) ? (CC - 1) : target[b * LL + t - 1];
        const int tok  = tokens[b * LL + t];
        tgt_part = (trans[prev * CC + tg] + st[tok * CC + tg]) * mask[b * LL + t];
    }

    // ---- E[k] = exp(trans[q*32+k][j]) in registers (each element read once) ----
    float E[32];
#pragma unroll
    for (int k = 0; k < 32; ++k)
        E[k] = __expf(trans[(q * 32 + k) * CC + j]);

    __syncthreads();   // tok_s/m_s visible

    // ---- init: p_1[j] = exp((trans[C-1][j] + em_0[j]) * m0) ----
    const float m0 = m_s[0];
    const int   si = ((j >> 5) * 36) + (j & 31);   // padded store index for state j
    float p = 0.0f;          // this thread's state value (meaningful on q==0)
    float ec = 1.0f;         // exp(em_t) for current step
    float en = 0.0f;         // raw em_{t+1}
    if (q == 0) {
        p = __expf((trans[(CC - 1) * CC + j] + st[tok_s[0] * CC + j]) * m0);
        p_s[0][si] = p;
        ec = __expf(st[tok_s[1] * CC + j]);
        en = st[tok_s[2] * CC + j];
    }
    float S = 0.0f;    // accumulated shift; true part[j] = log p[j] + S
    __syncthreads();

    // ---- sequential scan: exp-domain matvec, branchless, 1 bar/step ----
    for (int t = 1; t < LL; ++t) {
        const int   rb  = (t - 1) & 1, wb = t & 1;
        const float p0  = p_s[rb][0];          // normalizer (broadcast LDS)
        const float inv = frcp_ap(p0);         // overlaps the matvec
        const float mt  = m_s[t];

        // prefetch emission row for step t+2 (clamped; off critical path)
        const int   tpre = (t + 2 < LL) ? (t + 2) : (LL - 1);
        const float emr  = __ldg(&st[tok_s[tpre] * CC + j]);

        // matvec partial: s = sum_{k} p[q*32+k] * E[k]  (8 broadcast LDS.128)
        const float4* ap = reinterpret_cast<const float4*>(&p_s[rb][q * 36]);
        float s0 = 0.f, s1 = 0.f, s2 = 0.f, s3 = 0.f;
#pragma unroll
        for (int k = 0; k < 8; ++k) {
            const float4 v = ap[k];
            s0 = fmaf(v.x, E[4 * k + 0], s0);
            s1 = fmaf(v.y, E[4 * k + 1], s1);
            s2 = fmaf(v.z, E[4 * k + 2], s2);
            s3 = fmaf(v.w, E[4 * k + 3], s3);
        }
        float s = (s0 + s1) + (s2 + s3);
        s += __shfl_xor_sync(0xffffffffu, s, 8);    // combine quarters
        s += __shfl_xor_sync(0xffffffffu, s, 16);

        // normalized candidate + branchless masked blend (reference formula)
        const float pn = s * ec * inv;
        p += (pn - p) * mt;
        if (tid == 0) S += mt * __logf(p0);         // off-path, thread 0 only

        if (q == 0) p_s[wb][si] = p;

        ec = __expf(en);                            // exp for step t+1, off-path
        en = emr;
        __syncthreads();
    }

    // ---- epilogue: loss = S + log(sum_j p[j]) - tgt_energy ----
    float c = (q == 0) ? p : 0.0f;                  // each state counted once
#pragma unroll
    for (int o = 16; o; o >>= 1) c += __shfl_xor_sync(0xffffffffu, c, o);
    float tp = tgt_part;
#pragma unroll
    for (int o = 16; o; o >>= 1) tp += __shfl_xor_sync(0xffffffffu, tp, o);
    if (l == 0) { red_s[w] = c; red2_s[w] = tp; }
    __syncthreads();

    if (tid == 0) {
        float ss = 0.f, ts = 0.f;
#pragma unroll
        for (int i = 0; i < 16; ++i) { ss += red_s[i]; ts += red2_s[i]; }
        out[b] = S + logf(ss) - ts;
    }
}

extern "C" void kernel_launch(void* const* d_in, const int* in_sizes, int n_in,
                              void* d_out, int out_size)
{
    const int*   tokens = (const int*)  d_in[0];
    const int*   target = (const int*)  d_in[1];
    const float* mask   = (const float*)d_in[2];
    const float* st     = (const float*)d_in[3];
    const float* trans  = (const float*)d_in[4];
    float*       out    = (float*)d_out;

    const int B = in_sizes[0] / LL;   // 32
    crf_fwd_kernel<<<B, BDIM>>>(tokens, target, mask, st, trans, out);
}

// round 10
// speedup vs baseline: 1.3484x; 1.3484x over previous
#include <cuda_runtime.h>
#include <cuda_bf16.h>

// Problem constants (fixed by the dataset): B=32, L=256, V=50000, C=128
#define CC   128
#define LL   256
#define BDIM 128

typedef unsigned int u32;

__device__ __forceinline__ u32 bf2_fma(u32 a, u32 b, u32 c) {
    u32 d; asm("fma.rn.bf16x2 %0, %1, %2, %3;" : "=r"(d) : "r"(a), "r"(b), "r"(c)); return d;
}
__device__ __forceinline__ u32 bf2_pack(float lo, float hi) {
    // cvt.rn.bf16x2.f32 d, a, b -> d.hi = cvt(a), d.lo = cvt(b)
    u32 d; asm("cvt.rn.bf16x2.f32 %0, %1, %2;" : "=r"(d) : "f"(hi), "f"(lo)); return d;
}
__device__ __forceinline__ float bf2_lo(u32 v) { return __uint_as_float(v << 16); }
__device__ __forceinline__ float bf2_hi(u32 v) { return __uint_as_float(v & 0xFFFF0000u); }
__device__ __forceinline__ float frcp_ap(float x) {
    float r; asm("rcp.approx.f32 %0, %1;" : "=f"(r) : "f"(x)); return r;
}

__global__ __launch_bounds__(BDIM, 1)
void crf_fwd_kernel(const int*   __restrict__ tokens,
                    const int*   __restrict__ target,
                    const float* __restrict__ mask,
                    const float* __restrict__ st,      // state_table [V, C]
                    const float* __restrict__ trans,   // trans_matrix [C, C]
                    float*       __restrict__ out)     // [B]
{
    // p as duplicated bf16x2 {p_i, p_i}, one u32 per state i, double buffered.
    // Halves (i<64 / i>=64) start 68 words apart -> the two broadcast LDS.128
    // address groups hit disjoint banks for every k. 16B aligned for uint4.
    __shared__ __align__(16) u32 p2_s[2][136];
    __shared__ int   tok_s[LL];
    __shared__ float m_s[LL];
    __shared__ float red_s[4], red2_s[4];

    const int b    = blockIdx.x;
    const int tid  = threadIdx.x;
    const int w    = tid >> 5;
    const int l    = tid & 31;
    const int jp   = w * 16 + (l & 15);   // state-pair 0..63 -> states (2jp, 2jp+1)
    const int half = l >> 4;              // i-half: 64 terms each
    const int j0   = 2 * jp;

    // ---- stage tokens/mask (two rounds: LL = 2*BDIM) + target-energy partial ----
    float tgt_part = 0.0f;
#pragma unroll
    for (int t = tid; t < LL; t += BDIM) {
        tok_s[t] = tokens[b * LL + t];
        m_s[t]   = mask[b * LL + t];
        const int tg   = target[b * LL + t];
        const int prev = (t == 0) ? (CC - 1) : target[b * LL + t - 1];
        tgt_part += (trans[prev * CC + tg] + st[tok_s[t] * CC + tg]) * m_s[t];
    }

    // ---- E2[k] = bf16x2{ exp(trans[i][2jp]), exp(trans[i][2jp+1]) }, i = half*64+k ----
    u32 E2[64];
#pragma unroll
    for (int k = 0; k < 64; ++k) {
        const int i = half * 64 + k;
        const float2 tv = *reinterpret_cast<const float2*>(trans + i * CC + j0);
        E2[k] = bf2_pack(__expf(tv.x), __expf(tv.y));
    }
    __syncthreads();   // tok_s/m_s visible

    // ---- init: p_1[j] = exp((trans[C-1][j] + em_0[j]) * m0) ----
    const float m0 = m_s[0];
    const int   wi = j0 + ((j0 >> 6) << 2);   // padded store index (even -> 8B aligned)
    float p0r, p1r;
    {
        const float2 t127 = *reinterpret_cast<const float2*>(trans + (CC - 1) * CC + j0);
        const float2 e0   = *reinterpret_cast<const float2*>(st + tok_s[0] * CC + j0);
        p0r = __expf((t127.x + e0.x) * m0);
        p1r = __expf((t127.y + e0.y) * m0);
        if (half == 0)
            *reinterpret_cast<uint2*>(&p2_s[0][wi]) =
                make_uint2(bf2_pack(p0r, p0r), bf2_pack(p1r, p1r));
    }
    // emission exp pipeline (every thread: both halves run the update)
    float ec0, ec1, en0, en1;
    {
        const float2 e1 = *reinterpret_cast<const float2*>(st + tok_s[1] * CC + j0);
        const float2 e2 = *reinterpret_cast<const float2*>(st + tok_s[2] * CC + j0);
        ec0 = __expf(e1.x); ec1 = __expf(e1.y);
        en0 = __expf(e2.x); en1 = __expf(e2.y);
    }
    float S = 0.0f;    // accumulated shift; true part[j] = log p[j] + S
    __syncthreads();

    // ---- sequential scan: in-thread bf16x2 matvec, 1 shfl, 1 bar/step ----
    for (int t = 1; t < LL; ++t) {
        const int rb = (t - 1) & 1, wb = t & 1;

        const float p0  = bf2_lo(p2_s[rb][0]);     // normalizer (broadcast LDS)
        const float inv = frcp_ap(p0);             // overlaps the matvec
        const float mt  = m_s[t];

        // prefetch emission row (t+2, clamped) — off critical path
        const int tpre = (t + 2 < LL) ? (t + 2) : (LL - 1);
        const float2 emr =
            __ldg(reinterpret_cast<const float2*>(st + tok_s[tpre] * CC) + jp);

        // s_pair += {p_i,p_i} * {E[i][2jp], E[i][2jp+1]} over this half's 64 i's.
        // 8 independent bf16x2 accumulators, 8 terms each (same chain depth as R8).
        const uint4* ap = reinterpret_cast<const uint4*>(&p2_s[rb][half * 68]);
        u32 a0 = 0, a1 = 0, a2 = 0, a3 = 0, a4 = 0, a5 = 0, a6 = 0, a7 = 0;
#pragma unroll
        for (int k = 0; k < 8; ++k) {
            const uint4 v0 = ap[2 * k];
            const uint4 v1 = ap[2 * k + 1];
            a0 = bf2_fma(v0.x, E2[8 * k + 0], a0);
            a1 = bf2_fma(v0.y, E2[8 * k + 1], a1);
            a2 = bf2_fma(v0.z, E2[8 * k + 2], a2);
            a3 = bf2_fma(v0.w, E2[8 * k + 3], a3);
            a4 = bf2_fma(v1.x, E2[8 * k + 4], a4);
            a5 = bf2_fma(v1.y, E2[8 * k + 5], a5);
            a6 = bf2_fma(v1.z, E2[8 * k + 6], a6);
            a7 = bf2_fma(v1.w, E2[8 * k + 7], a7);
        }
        // fp32 combine of the 8 sub-sums (lo & hi lanes)
        float slo = ((bf2_lo(a0) + bf2_lo(a1)) + (bf2_lo(a2) + bf2_lo(a3)))
                  + ((bf2_lo(a4) + bf2_lo(a5)) + (bf2_lo(a6) + bf2_lo(a7)));
        float shi = ((bf2_hi(a0) + bf2_hi(a1)) + (bf2_hi(a2) + bf2_hi(a3)))
                  + ((bf2_hi(a4) + bf2_hi(a5)) + (bf2_hi(a6) + bf2_hi(a7)));
        // combine the two i-halves: partner lane is l ^ 16 (same warp)
        slo += __shfl_xor_sync(0xffffffffu, slo, 16);
        shi += __shfl_xor_sync(0xffffffffu, shi, 16);

        // branchless masked update (reference blend formula)
        const float pn0 = slo * ec0 * inv;
        const float pn1 = shi * ec1 * inv;
        p0r += (pn0 - p0r) * mt;
        p1r += (pn1 - p1r) * mt;
        if (tid == 0) S += mt * __logf(p0);        // off-path, thread 0 only

        if (half == 0)
            *reinterpret_cast<uint2*>(&p2_s[wb][wi]) =
                make_uint2(bf2_pack(p0r, p0r), bf2_pack(p1r, p1r));

        ec0 = en0; ec1 = en1;
        en0 = __expf(emr.x); en1 = __expf(emr.y);  // off-path (used at t+2)
        __syncthreads();
    }

    // ---- epilogue: loss = S + log(sum_j p[j]) - tgt_energy ----
    float c = (half == 0) ? (p0r + p1r) : 0.0f;    // each state counted once
#pragma unroll
    for (int o = 16; o; o >>= 1) c += __shfl_xor_sync(0xffffffffu, c, o);
    float tp = tgt_part;
#pragma unroll
    for (int o = 16; o; o >>= 1) tp += __shfl_xor_sync(0xffffffffu, tp, o);
    if (l == 0) { red_s[w] = c; red2_s[w] = tp; }
    __syncthreads();

    if (tid == 0) {
        const float ss = (red_s[0] + red_s[1]) + (red_s[2] + red_s[3]);
        const float ts = (red2_s[0] + red2_s[1]) + (red2_s[2] + red2_s[3]);
        out[b] = S + logf(ss) - ts;
    }
}

extern "C" void kernel_launch(void* const* d_in, const int* in_sizes, int n_in,
                              void* d_out, int out_size)
{
    const int*   tokens = (const int*)  d_in[0];
    const int*   target = (const int*)  d_in[1];
    const float* mask   = (const float*)d_in[2];
    const float* st     = (const float*)d_in[3];
    const float* trans  = (const float*)d_in[4];
    float*       out    = (float*)d_out;

    const int B = in_sizes[0] / LL;   // 32
    crf_fwd_kernel<<<B, BDIM>>>(tokens, target, mask, st, trans, out);
}

// round 11
// speedup vs baseline: 1.3645x; 1.0119x over previous
#include <cuda_runtime.h>
#include <cuda_bf16.h>

// Problem constants (fixed by the dataset): B=32, L=256, V=50000, C=128
#define CC   128
#define LL   256
#define BDIM 128

typedef unsigned int u32;

__device__ __forceinline__ u32 bf2_fma(u32 a, u32 b, u32 c) {
    u32 d; asm("fma.rn.bf16x2 %0, %1, %2, %3;" : "=r"(d) : "r"(a), "r"(b), "r"(c)); return d;
}
__device__ __forceinline__ u32 bf2_add(u32 a, u32 b) {
    u32 d; asm("add.rn.bf16x2 %0, %1, %2;" : "=r"(d) : "r"(a), "r"(b)); return d;
}
__device__ __forceinline__ u32 bf2_pack(float lo, float hi) {
    // cvt.rn.bf16x2.f32 d, a, b -> d.hi = cvt(a), d.lo = cvt(b)
    u32 d; asm("cvt.rn.bf16x2.f32 %0, %1, %2;" : "=r"(d) : "f"(hi), "f"(lo)); return d;
}
__device__ __forceinline__ float bf2_lo(u32 v) { return __uint_as_float(v << 16); }
__device__ __forceinline__ float bf2_hi(u32 v) { return __uint_as_float(v & 0xFFFF0000u); }
__device__ __forceinline__ float frcp_ap(float x) {
    float r; asm("rcp.approx.f32 %0, %1;" : "=f"(r) : "f"(x)); return r;
}

__global__ __launch_bounds__(BDIM, 1)
void crf_fwd_kernel(const int*   __restrict__ tokens,
                    const int*   __restrict__ target,
                    const float* __restrict__ mask,
                    const float* __restrict__ st,      // state_table [V, C]
                    const float* __restrict__ trans,   // trans_matrix [C, C]
                    float*       __restrict__ out)     // [B]
{
    // p as duplicated bf16x2 {p_i, p_i}, one u32 per state i, double buffered.
    // Halves (i<64 / i>=64) start 68 words apart -> the two broadcast LDS.128
    // address groups hit disjoint banks. 16B aligned for uint4 reads.
    __shared__ __align__(16) u32 p2_s[2][136];
    __shared__ int   tok_s[LL];
    __shared__ float m_s[LL];
    __shared__ float red_s[4], red2_s[4];

    const int b    = blockIdx.x;
    const int tid  = threadIdx.x;
    const int w    = tid >> 5;
    const int l    = tid & 31;
    const int jp   = w * 16 + (l & 15);   // state-pair 0..63 -> states (2jp, 2jp+1)
    const int half = l >> 4;              // i-half: 64 terms each
    const int j0   = 2 * jp;

    // ---- stage tokens/mask (LL = 2*BDIM) + target-energy partial ----
    float tgt_part = 0.0f;
#pragma unroll
    for (int t = tid; t < LL; t += BDIM) {
        tok_s[t] = tokens[b * LL + t];
        m_s[t]   = mask[b * LL + t];
        const int tg   = target[b * LL + t];
        const int prev = (t == 0) ? (CC - 1) : target[b * LL + t - 1];
        tgt_part += (trans[prev * CC + tg] + st[tok_s[t] * CC + tg]) * m_s[t];
    }

    // ---- E2[k] = bf16x2{ exp(trans[i][2jp]), exp(trans[i][2jp+1]) }, i = half*64+k ----
    u32 E2[64];
#pragma unroll
    for (int k = 0; k < 64; ++k) {
        const int i = half * 64 + k;
        const float2 tv = *reinterpret_cast<const float2*>(trans + i * CC + j0);
        E2[k] = bf2_pack(__expf(tv.x), __expf(tv.y));
    }
    __syncthreads();   // tok_s/m_s visible

    // ---- init: p_1[j] = exp((trans[C-1][j] + em_0[j]) * m0) ----
    const float m0 = m_s[0];
    const int   wi = j0 + ((j0 >> 6) << 2);   // padded store index
    float p0r, p1r;
    {
        const float2 t127 = *reinterpret_cast<const float2*>(trans + (CC - 1) * CC + j0);
        const float2 e0   = *reinterpret_cast<const float2*>(st + tok_s[0] * CC + j0);
        p0r = __expf((t127.x + e0.x) * m0);
        p1r = __expf((t127.y + e0.y) * m0);
        if (half == 0)
            *reinterpret_cast<uint2*>(&p2_s[0][wi]) =
                make_uint2(bf2_pack(p0r, p0r), bf2_pack(p1r, p1r));
    }
    // emission pipeline, depth 3:
    //   ec = exp(em[t]), en = exp(em[t+1]), raw = em[t+2] (raw float2)
    float  ec0, ec1, en0, en1;
    float2 raw;
    {
        const float2 e1 = *reinterpret_cast<const float2*>(st + tok_s[1] * CC + j0);
        const float2 e2 = *reinterpret_cast<const float2*>(st + tok_s[2] * CC + j0);
        raw             = *reinterpret_cast<const float2*>(st + tok_s[3] * CC + j0);
        ec0 = __expf(e1.x); ec1 = __expf(e1.y);
        en0 = __expf(e2.x); en1 = __expf(e2.y);
    }
    float S = 0.0f;    // accumulated shift; true part[j] = log p[j] + S
    __syncthreads();

    // ---- sequential scan: in-thread bf16x2 matvec, 1 shfl, 1 bar/step ----
    for (int t = 1; t < LL; ++t) {
        const int rb = (t - 1) & 1, wb = t & 1;

        const float p0  = bf2_lo(p2_s[rb][0]);     // normalizer (broadcast LDS)
        const float inv = frcp_ap(p0);             // overlaps the matvec
        const float mt  = m_s[t];

        // issue LDG for emission row t+3 (clamped) — consumed NEXT iteration,
        // so the L2 round-trip is fully hidden behind one whole step.
        const int tpre = (t + 3 < LL) ? (t + 3) : (LL - 1);
        const float2 emr =
            __ldg(reinterpret_cast<const float2*>(st + tok_s[tpre] * CC) + jp);

        // s_pair += {p_i,p_i} * {E[i][2jp], E[i][2jp+1]} over this half's 64 i's.
        const uint4* ap = reinterpret_cast<const uint4*>(&p2_s[rb][half * 68]);
        u32 a0 = 0, a1 = 0, a2 = 0, a3 = 0, a4 = 0, a5 = 0, a6 = 0, a7 = 0;
#pragma unroll
        for (int k = 0; k < 8; ++k) {
            const uint4 v0 = ap[2 * k];
            const uint4 v1 = ap[2 * k + 1];
            a0 = bf2_fma(v0.x, E2[8 * k + 0], a0);
            a1 = bf2_fma(v0.y, E2[8 * k + 1], a1);
            a2 = bf2_fma(v0.z, E2[8 * k + 2], a2);
            a3 = bf2_fma(v0.w, E2[8 * k + 3], a3);
            a4 = bf2_fma(v1.x, E2[8 * k + 4], a4);
            a5 = bf2_fma(v1.y, E2[8 * k + 5], a5);
            a6 = bf2_fma(v1.z, E2[8 * k + 6], a6);
            a7 = bf2_fma(v1.w, E2[8 * k + 7], a7);
        }
        // combine: one bf16x2 level (4 instrs), then fp32
        const u32 c0 = bf2_add(a0, a1), c1 = bf2_add(a2, a3);
        const u32 c2 = bf2_add(a4, a5), c3 = bf2_add(a6, a7);
        float slo = (bf2_lo(c0) + bf2_lo(c1)) + (bf2_lo(c2) + bf2_lo(c3));
        float shi = (bf2_hi(c0) + bf2_hi(c1)) + (bf2_hi(c2) + bf2_hi(c3));
        // combine the two i-halves: partner lane is l ^ 16 (same warp)
        slo += __shfl_xor_sync(0xffffffffu, slo, 16);
        shi += __shfl_xor_sync(0xffffffffu, shi, 16);

        // branchless masked update (reference blend formula)
        const float pn0 = slo * ec0 * inv;
        const float pn1 = shi * ec1 * inv;
        p0r += (pn0 - p0r) * mt;
        p1r += (pn1 - p1r) * mt;
        if (tid == 0) S += mt * __logf(p0);        // off-path, thread 0 only

        if (half == 0)
            *reinterpret_cast<uint2*>(&p2_s[wb][wi]) =
                make_uint2(bf2_pack(p0r, p0r), bf2_pack(p1r, p1r));

        // rotate emission pipeline: exp() consumes raw loaded LAST iteration
        ec0 = en0; ec1 = en1;
        en0 = __expf(raw.x); en1 = __expf(raw.y);
        raw = emr;
        __syncthreads();
    }

    // ---- epilogue: loss = S + log(sum_j p[j]) - tgt_energy ----
    float c = (half == 0) ? (p0r + p1r) : 0.0f;    // each state counted once
#pragma unroll
    for (int o = 16; o; o >>= 1) c += __shfl_xor_sync(0xffffffffu, c, o);
    float tp = tgt_part;
#pragma unroll
    for (int o = 16; o; o >>= 1) tp += __shfl_xor_sync(0xffffffffu, tp, o);
    if (l == 0) { red_s[w] = c; red2_s[w] = tp; }
    __syncthreads();

    if (tid == 0) {
        const float ss = (red_s[0] + red_s[1]) + (red_s[2] + red_s[3]);
        const float ts = (red2_s[0] + red2_s[1]) + (red2_s[2] + red2_s[3]);
        out[b] = S + logf(ss) - ts;
    }
}

extern "C" void kernel_launch(void* const* d_in, const int* in_sizes, int n_in,
                              void* d_out, int out_size)
{
    const int*   tokens = (const int*)  d_in[0];
    const int*   target = (const int*)  d_in[1];
    const float* mask   = (const float*)d_in[2];
    const float* st     = (const float*)d_in[3];
    const float* trans  = (const float*)d_in[4];
    float*       out    = (float*)d_out;

    const int B = in_sizes[0] / LL;   // 32
    crf_fwd_kernel<<<B, BDIM>>>(tokens, target, mask, st, trans, out);
}

// round 12
// speedup vs baseline: 1.9068x; 1.3974x over previous
#include <cuda_runtime.h>
#include <cuda_bf16.h>

// Problem constants (fixed by the dataset): B=32, L=256, V=50000, C=128
#define CC   128
#define LL   256
#define BDIM 128

typedef unsigned int u32;

__device__ __forceinline__ u32 bf2_fma(u32 a, u32 b, u32 c) {
    u32 d; asm("fma.rn.bf16x2 %0, %1, %2, %3;" : "=r"(d) : "r"(a), "r"(b), "r"(c)); return d;
}
__device__ __forceinline__ u32 bf2_add(u32 a, u32 b) {
    u32 d; asm("add.rn.bf16x2 %0, %1, %2;" : "=r"(d) : "r"(a), "r"(b)); return d;
}
__device__ __forceinline__ u32 bf2_pack(float lo, float hi) {
    // cvt.rn.bf16x2.f32 d, a, b -> d.hi = cvt(a), d.lo = cvt(b)
    u32 d; asm("cvt.rn.bf16x2.f32 %0, %1, %2;" : "=r"(d) : "f"(hi), "f"(lo)); return d;
}
__device__ __forceinline__ float bf2_lo(u32 v) { return __uint_as_float(v << 16); }
__device__ __forceinline__ float bf2_hi(u32 v) { return __uint_as_float(v & 0xFFFF0000u); }
__device__ __forceinline__ float frcp_ap(float x) {
    float r; asm("rcp.approx.f32 %0, %1;" : "=f"(r) : "f"(x)); return r;
}

__global__ __launch_bounds__(BDIM, 1)
void crf_fwd_kernel(const int*   __restrict__ tokens,
                    const int*   __restrict__ target,
                    const float* __restrict__ mask,
                    const float* __restrict__ st,      // state_table [V, C]
                    const float* __restrict__ trans,   // trans_matrix [C, C]
                    float*       __restrict__ out)     // [B]
{
    // p stored ONCE as bf16 pairs: word k = {p[2k](lo), p[2k+1](hi)}, 64 words,
    // double buffered. All threads read the same addresses (pure broadcast).
    __shared__ __align__(16) u32 p2_s[2][64];
    __shared__ int   tok_s[LL];
    __shared__ float m_s[LL];
    __shared__ float red_s[4], red2_s[4];

    const int b   = blockIdx.x;
    const int tid = threadIdx.x;
    const int w   = tid >> 5;
    const int l   = tid & 31;
    const int j   = tid;              // this thread owns state j (0..127)

    // ---- stage tokens/mask (LL = 2*BDIM) + target-energy partial ----
    float tgt_part = 0.0f;
#pragma unroll
    for (int t = tid; t < LL; t += BDIM) {
        tok_s[t] = tokens[b * LL + t];
        m_s[t]   = mask[b * LL + t];
        const int tg   = target[b * LL + t];
        const int prev = (t == 0) ? (CC - 1) : target[b * LL + t - 1];
        tgt_part += (trans[prev * CC + tg] + st[tok_s[t] * CC + tg]) * m_s[t];
    }

    // ---- E2[k] = bf16x2{ exp(trans[2k][j]), exp(trans[2k+1][j]) }, k = 0..63 ----
    u32 E2[64];
#pragma unroll
    for (int k = 0; k < 64; ++k)
        E2[k] = bf2_pack(__expf(trans[(2 * k) * CC + j]),
                         __expf(trans[(2 * k + 1) * CC + j]));
    __syncthreads();   // tok_s/m_s visible

    // ---- init: p_1[j] = exp((trans[C-1][j] + em_0[j]) * m0) ----
    __nv_bfloat16* pb0 = reinterpret_cast<__nv_bfloat16*>(&p2_s[0][0]);
    __nv_bfloat16* pb1 = reinterpret_cast<__nv_bfloat16*>(&p2_s[1][0]);
    const float m0 = m_s[0];
    float p = __expf((trans[(CC - 1) * CC + j] + st[tok_s[0] * CC + j]) * m0);
    pb0[j] = __float2bfloat16(p);

    // emission pipeline, depth 3: ec = exp(em[t]), en = exp(em[t+1]), raw = em[t+2]
    float ec  = __expf(st[tok_s[1] * CC + j]);
    float en  = __expf(st[tok_s[2] * CC + j]);
    float raw = st[tok_s[3] * CC + j];

    float S = 0.0f;    // accumulated shift; true part[j] = log p[j] + S
    __syncthreads();

    // ---- sequential scan: in-thread full matvec, 0 shfl, 1 bar/step ----
    for (int t = 1; t < LL; ++t) {
        const int rb = (t - 1) & 1, wb = t & 1;

        const float p0  = bf2_lo(p2_s[rb][0]);   // stored-bf16 normalizer (broadcast)
        const float inv = frcp_ap(p0);           // overlaps the matvec
        const float mt  = m_s[t];

        // issue LDG for emission row t+3 (clamped) — consumed NEXT iteration
        const int tpre = (t + 3 < LL) ? (t + 3) : (LL - 1);
        const float emr = __ldg(&st[tok_s[tpre] * CC + j]);

        // s_j = sum_i p[i] * E[i][j]: 64 HFMA2 over i-pairs, 8 indep chains
        const uint4* ap = reinterpret_cast<const uint4*>(&p2_s[rb][0]);
        u32 a0 = 0, a1 = 0, a2 = 0, a3 = 0, a4 = 0, a5 = 0, a6 = 0, a7 = 0;
#pragma unroll
        for (int k = 0; k < 8; ++k) {
            const uint4 v0 = ap[2 * k];
            const uint4 v1 = ap[2 * k + 1];
            a0 = bf2_fma(v0.x, E2[8 * k + 0], a0);
            a1 = bf2_fma(v0.y, E2[8 * k + 1], a1);
            a2 = bf2_fma(v0.z, E2[8 * k + 2], a2);
            a3 = bf2_fma(v0.w, E2[8 * k + 3], a3);
            a4 = bf2_fma(v1.x, E2[8 * k + 4], a4);
            a5 = bf2_fma(v1.y, E2[8 * k + 5], a5);
            a6 = bf2_fma(v1.z, E2[8 * k + 6], a6);
            a7 = bf2_fma(v1.w, E2[8 * k + 7], a7);
        }
        // one bf16x2 add level (4 instrs), then fp32 tree; s = lo-sum + hi-sum
        const u32 c0 = bf2_add(a0, a1), c1 = bf2_add(a2, a3);
        const u32 c2 = bf2_add(a4, a5), c3 = bf2_add(a6, a7);
        const float s = ((bf2_lo(c0) + bf2_lo(c1)) + (bf2_lo(c2) + bf2_lo(c3)))
                      + ((bf2_hi(c0) + bf2_hi(c1)) + (bf2_hi(c2) + bf2_hi(c3)));

        // branchless masked update (reference blend formula)
        const float pn = s * ec * inv;
        p += (pn - p) * mt;
        if (tid == 0) S += mt * __logf(p0);      // off-path, thread 0 only

        // single bf16 scalar store (adjacent threads fill one u32 word)
        ((wb) ? pb1 : pb0)[j] = __float2bfloat16(p);

        // rotate emission pipeline: exp consumes raw loaded LAST iteration
        ec  = en;
        en  = __expf(raw);
        raw = emr;
        __syncthreads();
    }

    // ---- epilogue: loss = S + log(sum_j p[j]) - tgt_energy ----
    float c = p;                                  // each state counted once
#pragma unroll
    for (int o = 16; o; o >>= 1) c += __shfl_xor_sync(0xffffffffu, c, o);
    float tp = tgt_part;
#pragma unroll
    for (int o = 16; o; o >>= 1) tp += __shfl_xor_sync(0xffffffffu, tp, o);
    if (l == 0) { red_s[w] = c; red2_s[w] = tp; }
    __syncthreads();

    if (tid == 0) {
        const float ss = (red_s[0] + red_s[1]) + (red_s[2] + red_s[3]);
        const float ts = (red2_s[0] + red2_s[1]) + (red2_s[2] + red2_s[3]);
        out[b] = S + logf(ss) - ts;
    }
}

extern "C" void kernel_launch(void* const* d_in, const int* in_sizes, int n_in,
                              void* d_out, int out_size)
{
    const int*   tokens = (const int*)  d_in[0];
    const int*   target = (const int*)  d_in[1];
    const float* mask   = (const float*)d_in[2];
    const float* st     = (const float*)d_in[3];
    const float* trans  = (const float*)d_in[4];
    float*       out    = (float*)d_out;

    const int B = in_sizes[0] / LL;   // 32
    crf_fwd_kernel<<<B, BDIM>>>(tokens, target, mask, st, trans, out);
}